// round 17
// baseline (speedup 1.0000x reference)
#include <cuda_runtime.h>
#include <math.h>
#include <stdint.h>

#define B_   4096
#define IN_  512
#define OUT_ 512
#define NC_  64
#define KA   576     // 512 (x|W) + 64 (rbf|c_sum)
#define NCH  18      // 576 / 32

#define STG_BYTES 24576u   // per stage: A 8KB + B 16KB
#define B_OFF     8192u    // B area offset within a stage

// ---------------- scratch (__device__ globals; no allocation allowed) -------
__device__ __align__(16) float g_Ax[B_ * IN_];     // tf32-RN rounded x
__device__ __align__(16) float g_Arbf[B_ * NC_];   // tf32-RN rounded rbf
__device__ __align__(16) float g_Bt[OUT_ * KA];    // row o: [W^T | c_sumT], rounded
__device__ float g_klpart[OUT_];

__device__ __forceinline__ float rna_tf32(float v) {
    uint32_t u;
    asm("cvt.rna.tf32.f32 %0, %1;" : "=r"(u) : "f"(v));
    return __uint_as_float(u);
}
__device__ __forceinline__ uint32_t smem_u32(const void* p) {
    uint32_t a;
    asm("{ .reg .u64 t; cvta.to.shared.u64 t, %1; cvt.u32.u64 %0, t; }" : "=r"(a) : "l"(p));
    return a;
}

// ---------------------------------------------------------------------------
// convert_w: transpose W[k][o] -> g_Bt[o][k], tf32-RN rounded.
// ---------------------------------------------------------------------------
__global__ void __launch_bounds__(256) convert_w_kernel(const float* __restrict__ W)
{
    __shared__ float tile[32][33];
    int tx = threadIdx.x & 31, ty = threadIdx.x >> 5;
    int bx = blockIdx.x, by = blockIdx.y;

    #pragma unroll
    for (int i = 0; i < 4; i++)
        tile[ty + i * 8][tx] = W[(size_t)(by * 32 + ty + i * 8) * OUT_ + bx * 32 + tx];
    __syncthreads();

    #pragma unroll
    for (int i = 0; i < 4; i++) {
        int o = bx * 32 + ty + i * 8;
        int k = by * 32 + tx;
        g_Bt[(size_t)o * KA + k] = rna_tf32(tile[tx][ty + i * 8]);
    }
}

// ---------------------------------------------------------------------------
// reduce_coeff: c_sum[o][n] = sum_i (mean + eps*std) + KL partials per o.
// DRAM-bound (201 MB). Writes rounded c_sumT into g_Bt[o][512+n].
// PDL primary: signals launch_dependents at the top so the (PDL-attributed)
// gemm may start its reduce-independent chunks while this kernel runs.
// ---------------------------------------------------------------------------
__global__ void __launch_bounds__(256) reduce_coeff_kernel(
    const float* __restrict__ cm, const float* __restrict__ clv,
    const float* __restrict__ ep)
{
    asm volatile("griddepcontrol.launch_dependents;");

    const int o = blockIdx.x, t = threadIdx.x;
    const int n4 = t & 15, isub = t >> 4;
    const float4* cm4  = (const float4*)cm;
    const float4* clv4 = (const float4*)clv;
    const float4* ep4  = (const float4*)ep;

    float4 ac = make_float4(0.f, 0.f, 0.f, 0.f);
    float akl = 0.f;
    #pragma unroll 4
    for (int i = isub; i < IN_; i += 16) {
        size_t idx = (size_t)i * 8192 + o * 16 + n4;   // float4 index
        float4 m  = __ldcs(cm4 + idx);
        float4 lv = __ldcs(clv4 + idx);
        float4 e  = __ldcs(ep4 + idx);
        float s0 = __expf(0.5f * lv.x), s1 = __expf(0.5f * lv.y);
        float s2 = __expf(0.5f * lv.z), s3 = __expf(0.5f * lv.w);
        ac.x += m.x + e.x * s0;  ac.y += m.y + e.y * s1;
        ac.z += m.z + e.z * s2;  ac.w += m.w + e.w * s3;
        akl += (s0*s0 + m.x*m.x - 1.f - lv.x) + (s1*s1 + m.y*m.y - 1.f - lv.y)
             + (s2*s2 + m.z*m.z - 1.f - lv.z) + (s3*s3 + m.w*m.w - 1.f - lv.w);
    }

    __shared__ float4 sc[16][16];   // [isub][n4]
    __shared__ float  sk[256];
    sc[isub][n4] = ac;
    sk[t] = akl;
    __syncthreads();

    if (t < 64) {
        float sum = 0.f;
        #pragma unroll
        for (int s2i = 0; s2i < 16; s2i++)
            sum += ((const float*)&sc[s2i][0])[t];
        g_Bt[(size_t)o * KA + 512 + t] = rna_tf32(sum);
    }
    if (t < 128) sk[t] += sk[t + 128];
    __syncthreads();
    if (t < 64) sk[t] += sk[t + 64];
    __syncthreads();
    if (t < 32) {
        float v = sk[t] + sk[t + 32];
        #pragma unroll
        for (int off = 16; off > 0; off >>= 1) v += __shfl_down_sync(0xffffffffu, v, off);
        if (t == 0) g_klpart[o] = v;
    }
}

// ---------------------------------------------------------------------------
// rbf_fused: dot = x.c SIMT GEMM + |c|^2 + sigma + tf32 passthrough of x.
// ---------------------------------------------------------------------------
__global__ void __launch_bounds__(256) rbf_fused_kernel(
    const float* __restrict__ x, const float* __restrict__ centers,
    const float* __restrict__ log_sigma)
{
    __shared__ float As[32][33];   // [k][row]
    __shared__ float Cs[32][68];   // [k][n]
    const int t = threadIdx.x;
    const int bm = blockIdx.x * 32;
    const int tx = t & 15, ty = t >> 4;

    float acc[2][4] = {{0.f,0.f,0.f,0.f},{0.f,0.f,0.f,0.f}};
    float sq0 = 0.f, sq1 = 0.f;
    float c2[4] = {0.f, 0.f, 0.f, 0.f};

    for (int kt = 0; kt < 16; kt++) {
        {   int row = t >> 3, kq = (t & 7) * 4;
            float4 v = *(const float4*)&x[(size_t)(bm + row) * IN_ + kt * 32 + kq];
            As[kq][row] = v.x; As[kq+1][row] = v.y; As[kq+2][row] = v.z; As[kq+3][row] = v.w;
            float4 rv = make_float4(rna_tf32(v.x), rna_tf32(v.y),
                                    rna_tf32(v.z), rna_tf32(v.w));
            *(float4*)&g_Ax[(size_t)(bm + row) * IN_ + kt * 32 + kq] = rv;
        }
        {   int n = t >> 2, kq = (t & 3) * 8;
            const float* src = &centers[(size_t)n * IN_ + kt * 32 + kq];
            float4 v0 = *(const float4*)src;
            float4 v1 = *(const float4*)(src + 4);
            Cs[kq  ][n] = v0.x; Cs[kq+1][n] = v0.y; Cs[kq+2][n] = v0.z; Cs[kq+3][n] = v0.w;
            Cs[kq+4][n] = v1.x; Cs[kq+5][n] = v1.y; Cs[kq+6][n] = v1.z; Cs[kq+7][n] = v1.w;
        }
        __syncthreads();
        #pragma unroll
        for (int k = 0; k < 32; k++) {
            float a0 = As[k][ty * 2], a1 = As[k][ty * 2 + 1];
            float4 c = *(const float4*)&Cs[k][tx * 4];
            acc[0][0] += a0 * c.x; acc[0][1] += a0 * c.y;
            acc[0][2] += a0 * c.z; acc[0][3] += a0 * c.w;
            acc[1][0] += a1 * c.x; acc[1][1] += a1 * c.y;
            acc[1][2] += a1 * c.z; acc[1][3] += a1 * c.w;
            sq0 += a0 * a0; sq1 += a1 * a1;
            c2[0] += c.x * c.x; c2[1] += c.y * c.y;
            c2[2] += c.z * c.z; c2[3] += c.w * c.w;
        }
        __syncthreads();
    }

    float inv[4];
    #pragma unroll
    for (int j = 0; j < 4; j++) {
        float sg = __expf(log_sigma[tx * 4 + j]);
        inv[j] = 1.0f / (2.0f * sg * sg + 1e-8f);
    }
    #pragma unroll
    for (int i = 0; i < 2; i++) {
        float sq = i ? sq1 : sq0;
        size_t base = (size_t)(bm + ty * 2 + i) * NC_;
        #pragma unroll
        for (int j = 0; j < 4; j++) {
            float d2 = sq - 2.f * acc[i][j] + c2[j];
            g_Arbf[base + tx * 4 + j] = rna_tf32(__expf(-d2 * inv[j]));
        }
    }
}

// ---------------------------------------------------------------------------
// tf32 mma GEMM: out[4096x512] = [g_Ax | g_Arbf] @ g_Bt^T, K = 576.
// 64x128 CTA tile (grid 4x64 = 256 CTAs, 3 CTAs/SM). 8 warps as 2(M)x4(N),
// warp tile 32x32. 3-stage cp.async pipeline, XOR-swizzled fp32 smem.
// PDL secondary: overlaps chunks 0..15 (independent of reduce_coeff) with the
// still-running reduce; griddepcontrol.wait before prefetching chunk 16
// (which reads g_Bt cols 512+) and before the fused KL read.
// ---------------------------------------------------------------------------
#define LOADC(c, stg) do {                                                    \
    uint32_t base_ = sb + (uint32_t)(stg) * STG_BYTES;                        \
    if (t < 128) {  /* A: 64 rows x 32 floats */                              \
        const float* pa = ((c) < 16)                                          \
            ? g_Ax + (size_t)(bm + lrow) * IN_ + (c) * 32                     \
            : g_Arbf + (size_t)(bm + lrow) * NC_ + ((c) - 16) * 32;           \
        uint32_t ab = base_ + (uint32_t)lrow * 128u;                          \
        _Pragma("unroll")                                                     \
        for (int j = 0; j < 4; j++) {                                         \
            uint32_t u = (uint32_t)(lu0 + j), ph = (u ^ swz) << 4;            \
            asm volatile("cp.async.cg.shared.global [%0], [%1], 16;"          \
                         :: "r"(ab + ph), "l"(pa + u * 4) : "memory");        \
        }                                                                     \
    }                                                                         \
    {   /* B: 128 rows x 32 floats */                                         \
        const float* pb = gB + (c) * 32;                                      \
        uint32_t bb = base_ + B_OFF + (uint32_t)lrow * 128u;                  \
        _Pragma("unroll")                                                     \
        for (int j = 0; j < 4; j++) {                                         \
            uint32_t u = (uint32_t)(lu0 + j), ph = (u ^ swz) << 4;            \
            asm volatile("cp.async.cg.shared.global [%0], [%1], 16;"          \
                         :: "r"(bb + ph), "l"(pb + u * 4) : "memory");        \
        }                                                                     \
    }                                                                         \
} while (0)

__global__ void __launch_bounds__(256, 3) gemm_tf32_kernel(float* __restrict__ out,
                                                           int out_size)
{
    extern __shared__ __align__(1024) char sm[];   // 3 stages x 24KB
    const int t = threadIdx.x, lane = t & 31, wid = t >> 5;
    const int wm = wid & 1, wn = wid >> 1;         // 2(M) x 4(N)
    const int bm = blockIdx.y * 64, bn = blockIdx.x * 128;
    const uint32_t sb = smem_u32(sm);

    // cp.async mapping
    const int lrow = t >> 1;                       // A rows: t<128 -> 0..63
    const int lu0  = (t & 1) * 4;
    const uint32_t swz = (uint32_t)(lrow & 7);
    const float* gB = g_Bt + (size_t)(bn + lrow) * KA;

    // ldmatrix per-lane geometry (8x8 b16 matrix == 8 rows x 4 fp32)
    const int arow_off = (lane & 7) + 8 * ((lane >> 3) & 1);
    const int a_uo = lane >> 4;            // 0/1 : k cols 0-3 / 4-7
    const int brow_off = lane & 7;
    const int b_uo = (lane >> 3) & 1;

    float acc[2][4][4];
    #pragma unroll
    for (int mt = 0; mt < 2; mt++)
        #pragma unroll
        for (int nt = 0; nt < 4; nt++)
            #pragma unroll
            for (int r = 0; r < 4; r++) acc[mt][nt][r] = 0.f;

    LOADC(0, 0);
    asm volatile("cp.async.commit_group;" ::: "memory");
    LOADC(1, 1);
    asm volatile("cp.async.commit_group;" ::: "memory");

    #pragma unroll 1
    for (int c = 0; c < NCH; c++) {
        asm volatile("cp.async.wait_group 1;" ::: "memory");
        __syncthreads();
        // chunk 16 (first reduce-dependent chunk) is prefetched at c == 14:
        // block here until reduce_coeff's writes are complete & visible.
        if (c == 14)
            asm volatile("griddepcontrol.wait;" ::: "memory");
        // prefetch chunk c+2 into stage (c+2)%3 (drained at iter c-1)
        if (c + 2 < NCH) LOADC(c + 2, (c + 2) % 3);
        asm volatile("cp.async.commit_group;" ::: "memory");

        const uint32_t st = sb + (uint32_t)(c % 3) * STG_BYTES;
        #pragma unroll
        for (int ks = 0; ks < 4; ks++) {
            uint32_t a[2][4], b[4][2];
            #pragma unroll
            for (int mt = 0; mt < 2; mt++) {
                int row = wm * 32 + mt * 16 + arow_off;
                uint32_t u = (uint32_t)(ks * 2 + a_uo);
                uint32_t ad = st + (uint32_t)row * 128u +
                              ((u ^ (uint32_t)(row & 7)) << 4);
                asm volatile(
                    "ldmatrix.sync.aligned.m8n8.x4.shared.b16 {%0,%1,%2,%3}, [%4];"
                    : "=r"(a[mt][0]), "=r"(a[mt][1]), "=r"(a[mt][2]), "=r"(a[mt][3])
                    : "r"(ad));
            }
            #pragma unroll
            for (int nt = 0; nt < 4; nt++) {
                int row = wn * 32 + nt * 8 + brow_off;
                uint32_t u = (uint32_t)(ks * 2 + b_uo);
                uint32_t bd = st + B_OFF + (uint32_t)row * 128u +
                              ((u ^ (uint32_t)(row & 7)) << 4);
                asm volatile(
                    "ldmatrix.sync.aligned.m8n8.x2.shared.b16 {%0,%1}, [%2];"
                    : "=r"(b[nt][0]), "=r"(b[nt][1])
                    : "r"(bd));
            }
            #pragma unroll
            for (int mt = 0; mt < 2; mt++)
                #pragma unroll
                for (int nt = 0; nt < 4; nt++)
                    asm volatile(
                        "mma.sync.aligned.m16n8k8.row.col.f32.tf32.tf32.f32 "
                        "{%0,%1,%2,%3}, {%4,%5,%6,%7}, {%8,%9}, {%0,%1,%2,%3};"
                        : "+f"(acc[mt][nt][0]), "+f"(acc[mt][nt][1]),
                          "+f"(acc[mt][nt][2]), "+f"(acc[mt][nt][3])
                        : "r"(a[mt][0]), "r"(a[mt][1]), "r"(a[mt][2]), "r"(a[mt][3]),
                          "r"(b[nt][0]), "r"(b[nt][1]));
        }
    }

    // fused KL scalar (g_klpart complete: all threads passed griddepcontrol.wait)
    if (blockIdx.x == 0 && blockIdx.y == 0 && t < 32) {
        float v = 0.f;
        for (int i = lane; i < OUT_; i += 32) v += g_klpart[i];
        #pragma unroll
        for (int off = 16; off > 0; off >>= 1) v += __shfl_down_sync(0xffffffffu, v, off);
        if (lane == 0) out[out_size - 1] = 0.5f * v;
    }

    // epilogue
    const int er = lane >> 2, ec = (lane & 3) * 2;
    #pragma unroll
    for (int mt = 0; mt < 2; mt++) {
        int r0 = bm + wm * 32 + mt * 16 + er;
        #pragma unroll
        for (int nt = 0; nt < 4; nt++) {
            int col = bn + wn * 32 + nt * 8 + ec;
            *(float2*)&out[(size_t)r0 * OUT_ + col] =
                make_float2(acc[mt][nt][0], acc[mt][nt][1]);
            *(float2*)&out[(size_t)(r0 + 8) * OUT_ + col] =
                make_float2(acc[mt][nt][2], acc[mt][nt][3]);
        }
    }
}

// ---------------------------------------------------------------------------
// Single stream. gemm launched with the PDL (programmatic stream
// serialization) attribute so it overlaps the reduce; if the attribute is
// ignored, execution degrades to the proven serial order (still correct).
// ---------------------------------------------------------------------------
extern "C" void kernel_launch(void* const* d_in, const int* in_sizes, int n_in,
                              void* d_out, int out_size)
{
    const float* x         = (const float*)d_in[0];
    const float* centers   = (const float*)d_in[1];
    const float* log_sigma = (const float*)d_in[2];
    const float* cm        = (const float*)d_in[3];
    const float* clv       = (const float*)d_in[4];
    const float* W         = (const float*)d_in[5];
    const float* ep        = (const float*)d_in[6];
    float* out = (float*)d_out;

    cudaFuncSetAttribute(gemm_tf32_kernel,
                         cudaFuncAttributeMaxDynamicSharedMemorySize, 3 * STG_BYTES);

    convert_w_kernel<<<dim3(16, 16), 256>>>(W);
    rbf_fused_kernel<<<128, 256>>>(x, centers, log_sigma);
    reduce_coeff_kernel<<<512, 256>>>(cm, clv, ep);   // PDL primary

    cudaLaunchConfig_t cfg = {};
    cfg.gridDim = dim3(OUT_ / 128, B_ / 64);
    cfg.blockDim = dim3(256);
    cfg.dynamicSmemBytes = 3 * STG_BYTES;
    cfg.stream = 0;
    cudaLaunchAttribute attr[1];
    attr[0].id = cudaLaunchAttributeProgrammaticStreamSerialization;
    attr[0].val.programmaticStreamSerializationAllowed = 1;
    cfg.attrs = attr;
    cfg.numAttrs = 1;
    cudaLaunchKernelEx(&cfg, gemm_tf32_kernel, out, out_size);
}